// round 14
// baseline (speedup 1.0000x reference)
#include <cuda_runtime.h>

#define B_    32
#define N_    8192
#define HD    256     // H_DIM
#define GH    512     // G_HID
#define GD    256     // G_DIM
#define KC    64      // K
#define CHUNK 128     // N_/KC
#define ROWS  129     // 2K+1
#define M_TOT 4128    // B_*ROWS

typedef unsigned long long u64;

// Scratch (static device globals — no allocation allowed)
__device__ float d_Hk[B_ * KC * HD];   // 2 MB   compact Hk rows
__device__ float d_y [B_ * GH];        // 64 KB  hn @ W1
__device__ float d_h1[M_TOT * GH];     // 8.4 MB
__device__ float d_gs[M_TOT * GD];     // 4.2 MB
__device__ float d_Sp[4 * B_ * GD];

// ---------------------------------------------------------------------------
// packed f32x2 helpers
// ---------------------------------------------------------------------------
__device__ __forceinline__ void ffma2(u64& d, u64 a, u64 b) {
    asm("fma.rn.f32x2 %0, %1, %2, %0;" : "+l"(d) : "l"(a), "l"(b));
}
__device__ __forceinline__ float2 unpk(u64 v) {
    unsigned lo, hi;
    asm("mov.b64 {%0, %1}, %2;" : "=r"(lo), "=r"(hi) : "l"(v));
    return make_float2(__uint_as_float(lo), __uint_as_float(hi));
}

// ---------------------------------------------------------------------------
// Kernel 0 (idx0): prep — y[b] = hn[b] @ W1 ; h1 row 2K = relu(y+b1); mask.
// Grid (4, B), 128 threads: block (nc,b) covers n = nc*128 .. +127.
// ---------------------------------------------------------------------------
__global__ __launch_bounds__(128)
void prep_kernel(const float* __restrict__ hs,
                 const int*   __restrict__ np,
                 const float* __restrict__ W1,
                 const float* __restrict__ b1,
                 float* __restrict__ out)
{
    const int nc  = blockIdx.x;
    const int b   = blockIdx.y;
    const int tid = threadIdx.x;
    const int n   = nc * 128 + tid;

    __shared__ float hn_s[HD];
    const int nrow = *np;
    for (int i = tid; i < HD; i += 128)
        hn_s[i] = hs[((size_t)b * N_ + nrow) * HD + i];
    __syncthreads();

    float a0 = 0.f, a1 = 0.f, a2 = 0.f, a3 = 0.f;
#pragma unroll 4
    for (int h = 0; h < HD; h += 4) {
        a0 += hn_s[h]     * W1[(size_t)h       * GH + n];
        a1 += hn_s[h + 1] * W1[(size_t)(h + 1) * GH + n];
        a2 += hn_s[h + 2] * W1[(size_t)(h + 2) * GH + n];
        a3 += hn_s[h + 3] * W1[(size_t)(h + 3) * GH + n];
    }
    const float y = (a0 + a1) + (a2 + a3);
    d_y[(size_t)b * GH + n] = y;
    d_h1[((size_t)b * ROWS + 2 * KC) * GH + n] = fmaxf(y + b1[n], 0.f);

    if (nc == 0 && b == 0) {
        float* mask = out + (size_t)B_ * (KC + 1) * GD;
        for (int i = tid; i < B_ * (KC + 1); i += 128)
            mask[i] = 1.0f;
    }
}

// ---------------------------------------------------------------------------
// Kernel 1 (idx1): clustered reduction -> compact d_Hk. Grid (K,B), 512 thr.
// ---------------------------------------------------------------------------
__global__ __launch_bounds__(512)
void reduce_kernel(const float* __restrict__ hs,
                   const int*   __restrict__ cs,
                   const int*   __restrict__ n_ptr)
{
    const int k    = blockIdx.x;
    const int b    = blockIdx.y;
    const int tid  = threadIdx.x;
    const int lane = tid & 63;
    const int grp  = tid >> 6;
    const int base = k * CHUNK;

    __shared__ int    scs[CHUNK];
    __shared__ int    sn;
    __shared__ float4 sm[8][64];

    if (tid < CHUNK) scs[tid] = cs[base + tid];
    if (tid == 0)    sn = *n_ptr;
    __syncthreads();

    const int n = sn;
    const float* p = hs + ((size_t)b * N_ + base) * HD + lane * 4;

    float4 s = make_float4(0.f, 0.f, 0.f, 0.f);
#pragma unroll 16
    for (int i = grp; i < CHUNK; i += 8) {
        float4 v = *(const float4*)(p + (size_t)i * HD);   // always in-bounds
        if (((base + i) < n) & (scs[i] == k)) {
            s.x += v.x; s.y += v.y; s.z += v.z; s.w += v.w;
        }
    }
    sm[grp][lane] = s;
    __syncthreads();

    if (grp == 0) {
        float4 t = sm[0][lane];
#pragma unroll
        for (int g = 1; g < 8; ++g) {
            float4 u = sm[g][lane];
            t.x += u.x; t.y += u.y; t.z += u.z; t.w += u.w;
        }
        ((float4*)(d_Hk + (size_t)(b * KC + k) * HD))[lane] = t;
    }
}

// ---------------------------------------------------------------------------
// GEMM 64x64 tile, BK=16, 256 threads, 2 CTAs/SM, double-buffered,
// PRE-DUPLICATED A smem: inner loop = 3 LDS.128 + 8 FFMA2, zero MOVs.
// DUAL: gemm1 mode — A = Hk (M=2048, by = batch), writes relu(X+b1) and
//       relu(X+y+b1) rows into d_h1. Plain: standard C row write.
// ---------------------------------------------------------------------------
#define ASTR 132                       // floats per dup-A row (16B aligned)
#define ABUF (16 * ASTR)
#define BSTR 68
#define BBUF (16 * BSTR)

template<bool DUAL, bool RELU>
__global__ __launch_bounds__(256, 2)
void gemm64_kernel(const float* __restrict__ A,
                   const float* __restrict__ W,
                   const float* __restrict__ bias,
                   float* __restrict__ C,
                   int M, int Nn, int Ktot)
{
    __shared__ float As2[2 * ABUF];    // duplicated A: 2*16*132*4 = 16.9 KB
    __shared__ float Bs [2 * BBUF];    // 8.7 KB

    const int tid = threadIdx.x;
    const int tx  = tid & 15;
    const int ty  = tid >> 4;
    const int m0  = blockIdx.y * 64;
    const int n0  = blockIdx.x * 64;

    // A loader: 4 threads/row, one float4 each
    const int ar = tid >> 2;           // 0..63
    const int ac = (tid & 3) * 4;      // 0,4,8,12
    const bool a_ok = (m0 + ar) < M;
    const float* aptr = A + (size_t)(m0 + ar) * Ktot + ac;

    // B loader: one float4 per thread
    const int brow = tid >> 4;         // 0..15
    const int bcol = (tid & 15) * 4;
    const float* wptr = W + (size_t)brow * Nn + n0 + bcol;

    u64 acc[4][2];
#pragma unroll
    for (int i = 0; i < 4; ++i) { acc[i][0] = 0ull; acc[i][1] = 0ull; }

    // prologue
    float4 pa = make_float4(0,0,0,0);
    if (a_ok) pa = *(const float4*)aptr;
    float4 pb = *(const float4*)wptr;

    {
        float av[4] = {pa.x, pa.y, pa.z, pa.w};
#pragma unroll
        for (int j = 0; j < 4; ++j)
            *(float2*)&As2[(ac + j) * ASTR + 2 * ar] = make_float2(av[j], av[j]);
        *(float4*)&Bs[brow * BSTR + bcol] = pb;
    }
    __syncthreads();

    int buf = 0;
    for (int k0 = 0; k0 < Ktot; k0 += 16) {
        const int k1 = k0 + 16;
        const bool more = (k1 < Ktot);

        if (more) {
            if (a_ok) pa = *(const float4*)(aptr + k1);
            pb = *(const float4*)(wptr + (size_t)k1 * Nn);
        }

        const float* Ab = As2 + buf * ABUF;
        const float* Bb = Bs  + buf * BBUF;
#pragma unroll
        for (int kk = 0; kk < 16; ++kk) {
            const u64* ap = (const u64*)(Ab + kk * ASTR + ty * 8);
            const u64 ad0 = ap[0], ad1 = ap[1], ad2 = ap[2], ad3 = ap[3];
            const u64* bp = (const u64*)(Bb + kk * BSTR + tx * 4);
            const u64 b0 = bp[0], b1v = bp[1];
            ffma2(acc[0][0], ad0, b0); ffma2(acc[0][1], ad0, b1v);
            ffma2(acc[1][0], ad1, b0); ffma2(acc[1][1], ad1, b1v);
            ffma2(acc[2][0], ad2, b0); ffma2(acc[2][1], ad2, b1v);
            ffma2(acc[3][0], ad3, b0); ffma2(acc[3][1], ad3, b1v);
        }

        if (more) {
            const int nb = buf ^ 1;
            float* An = As2 + nb * ABUF;
            float* Bn = Bs  + nb * BBUF;
            float av[4] = {pa.x, pa.y, pa.z, pa.w};
#pragma unroll
            for (int j = 0; j < 4; ++j)
                *(float2*)&An[(ac + j) * ASTR + 2 * ar] = make_float2(av[j], av[j]);
            *(float4*)&Bn[brow * BSTR + bcol] = pb;
            __syncthreads();
            buf = nb;
        }
    }

    // epilogue
    const int gn0 = n0 + tx * 4;
    const float4 bv = *(const float4*)(bias + gn0);

    if (DUAL) {
        // gemm1: by = batch, rows = k 0..63; write relu(X+b1) & relu(X+y+b1)
        const int b = blockIdx.y;
        const float4 yv = *(const float4*)(d_y + (size_t)b * GH + gn0);
        float* h1b = d_h1 + (size_t)b * ROWS * GH + gn0;
#pragma unroll
        for (int i = 0; i < 4; ++i) {
            const int k = ty * 4 + i;
            float2 p0 = unpk(acc[i][0]), p1 = unpk(acc[i][1]);
            float x0 = p0.x + bv.x, x1 = p0.y + bv.y;
            float x2 = p1.x + bv.z, x3 = p1.y + bv.w;
            *(float4*)(h1b + (size_t)k * GH) = make_float4(
                fmaxf(x0, 0.f), fmaxf(x1, 0.f), fmaxf(x2, 0.f), fmaxf(x3, 0.f));
            *(float4*)(h1b + (size_t)(KC + k) * GH) = make_float4(
                fmaxf(x0 + yv.x, 0.f), fmaxf(x1 + yv.y, 0.f),
                fmaxf(x2 + yv.z, 0.f), fmaxf(x3 + yv.w, 0.f));
        }
    } else {
#pragma unroll
        for (int i = 0; i < 4; ++i) {
            const int gm = m0 + ty * 4 + i;
            if (gm >= M) continue;
            float2 p0 = unpk(acc[i][0]), p1 = unpk(acc[i][1]);
            float o0 = p0.x + bv.x, o1 = p0.y + bv.y;
            float o2 = p1.x + bv.z, o3 = p1.y + bv.w;
            if (RELU) {
                o0 = fmaxf(o0, 0.f); o1 = fmaxf(o1, 0.f);
                o2 = fmaxf(o2, 0.f); o3 = fmaxf(o3, 0.f);
            }
            *(float4*)(C + (size_t)gm * Nn + gn0) = make_float4(o0, o1, o2, o3);
        }
    }
}

// ---------------------------------------------------------------------------
// Kernel 4: partial S. Grid (4, B).
// ---------------------------------------------------------------------------
__global__ void s_partial_kernel()
{
    const int q = blockIdx.x;
    const int b = blockIdx.y;
    const int h = threadIdx.x;
    const float* g = d_gs + (size_t)b * ROWS * GD;

    float s = 0.f;
#pragma unroll
    for (int j = q * 16; j < q * 16 + 16; ++j)
        s += g[(size_t)j * GD + h];
    d_Sp[((size_t)q * B_ + b) * GD + h] = s;
}

// ---------------------------------------------------------------------------
// Kernel 5: finalize. Grid (K+1, B), 256 threads.
// ---------------------------------------------------------------------------
__global__ void finalize_kernel(float* __restrict__ out)
{
    const int k = blockIdx.x;
    const int b = blockIdx.y;
    const int h = threadIdx.x;

    float S = d_Sp[((size_t)0 * B_ + b) * GD + h]
            + d_Sp[((size_t)1 * B_ + b) * GD + h]
            + d_Sp[((size_t)2 * B_ + b) * GD + h]
            + d_Sp[((size_t)3 * B_ + b) * GD + h];

    const float* g = d_gs + (size_t)b * ROWS * GD;

    float v;
    if (k < KC)
        v = S - g[(size_t)k * GD + h] + g[(size_t)(KC + k) * GD + h];
    else
        v = S + g[(size_t)(2 * KC) * GD + h];
    out[((size_t)b * (KC + 1) + k) * GD + h] = v;
}

// ---------------------------------------------------------------------------
extern "C" void kernel_launch(void* const* d_in, const int* in_sizes, int n_in,
                              void* d_out, int out_size)
{
    const float* hs = (const float*)d_in[0];
    const int*   cs = (const int*)  d_in[1];
    const float* W1 = (const float*)d_in[2];
    const float* b1 = (const float*)d_in[3];
    const float* W2 = (const float*)d_in[4];
    const float* b2 = (const float*)d_in[5];
    const int*   np = (const int*)  d_in[6];
    float* out = (float*)d_out;

    float *pHk, *pH1, *pGS;
    cudaGetSymbolAddress((void**)&pHk, d_Hk);
    cudaGetSymbolAddress((void**)&pH1, d_h1);
    cudaGetSymbolAddress((void**)&pGS, d_gs);

    // idx0: prep (y = hn@W1, h1 row 2K, mask)
    prep_kernel<<<dim3(4, B_), 128>>>(hs, np, W1, b1, out);

    // idx1: clustered reduce -> compact Hk
    reduce_kernel<<<dim3(KC, B_), 512>>>(hs, cs, np);

    // idx2: gemm1 X = Hk@W1 (M=2048), dual relu outputs (256 CTAs, 2/SM)
    gemm64_kernel<true, true><<<dim3(GH / 64, B_), 256>>>(pHk, W1, b1, nullptr, B_ * KC, GH, HD);

    // idx3: gemm2 [4128,512]@[512,256]+b2 (260 CTAs, 2/SM)   <- profiled slot
    gemm64_kernel<false, false><<<dim3(GD / 64, (M_TOT + 63) / 64), 256>>>(pH1, W2, b2, pGS, M_TOT, GD, GH);

    // idx4: S partials
    s_partial_kernel<<<dim3(4, B_), 256>>>();

    // idx5: finalize
    finalize_kernel<<<dim3(KC + 1, B_), 256>>>(out);
}

// round 15
// speedup vs baseline: 1.1651x; 1.1651x over previous
#include <cuda_runtime.h>

#define B_    32
#define N_    8192
#define HD    256     // H_DIM
#define GH    512     // G_HID
#define GD    256     // G_DIM
#define KC    64      // K
#define CHUNK 128     // N_/KC
#define ROWS  129     // 2K+1
#define M_TOT 4128    // B_*ROWS

typedef unsigned long long u64;

// Scratch (static device globals — no allocation allowed)
__device__ float d_Hk[B_ * KC * HD];       // 2 MB   compact Hk rows
__device__ float d_y [B_ * GH];            // 64 KB  hn @ W1
__device__ float d_h1[M_TOT * GH];         // 8.4 MB
__device__ float d_gs[2 * M_TOT * GD];     // 8.4 MB (split-K partials)
__device__ float d_Sp[4 * B_ * GD];

// ---------------------------------------------------------------------------
// packed f32x2 helpers
// ---------------------------------------------------------------------------
__device__ __forceinline__ u64 dup2(float x) {
    unsigned xi = __float_as_uint(x);
    u64 r;
    asm("mov.b64 %0, {%1, %1};" : "=l"(r) : "r"(xi));
    return r;
}
__device__ __forceinline__ void ffma2(u64& d, u64 a, u64 b) {
    asm("fma.rn.f32x2 %0, %1, %2, %0;" : "+l"(d) : "l"(a), "l"(b));
}
__device__ __forceinline__ float2 unpk(u64 v) {
    unsigned lo, hi;
    asm("mov.b64 {%0, %1}, %2;" : "=r"(lo), "=r"(hi) : "l"(v));
    return make_float2(__uint_as_float(lo), __uint_as_float(hi));
}

// ---------------------------------------------------------------------------
// Kernel 0 (idx0): prep — y[b] = hn[b] @ W1; h1 row 2K = relu(y+b1); mask.
// ---------------------------------------------------------------------------
__global__ __launch_bounds__(128)
void prep_kernel(const float* __restrict__ hs,
                 const int*   __restrict__ np,
                 const float* __restrict__ W1,
                 const float* __restrict__ b1,
                 float* __restrict__ out)
{
    const int nc  = blockIdx.x;
    const int b   = blockIdx.y;
    const int tid = threadIdx.x;
    const int n   = nc * 128 + tid;

    __shared__ float hn_s[HD];
    const int nrow = *np;
    for (int i = tid; i < HD; i += 128)
        hn_s[i] = hs[((size_t)b * N_ + nrow) * HD + i];
    __syncthreads();

    float a0 = 0.f, a1 = 0.f, a2 = 0.f, a3 = 0.f;
#pragma unroll 4
    for (int h = 0; h < HD; h += 4) {
        a0 += hn_s[h]     * W1[(size_t)h       * GH + n];
        a1 += hn_s[h + 1] * W1[(size_t)(h + 1) * GH + n];
        a2 += hn_s[h + 2] * W1[(size_t)(h + 2) * GH + n];
        a3 += hn_s[h + 3] * W1[(size_t)(h + 3) * GH + n];
    }
    const float y = (a0 + a1) + (a2 + a3);
    d_y[(size_t)b * GH + n] = y;
    d_h1[((size_t)b * ROWS + 2 * KC) * GH + n] = fmaxf(y + b1[n], 0.f);

    if (nc == 0 && b == 0) {
        float* mask = out + (size_t)B_ * (KC + 1) * GD;
        for (int i = tid; i < B_ * (KC + 1); i += 128)
            mask[i] = 1.0f;
    }
}

// ---------------------------------------------------------------------------
// Kernel 1 (idx1): clustered reduction -> compact d_Hk. Grid (K,B), 512 thr.
// ---------------------------------------------------------------------------
__global__ __launch_bounds__(512)
void reduce_kernel(const float* __restrict__ hs,
                   const int*   __restrict__ cs,
                   const int*   __restrict__ n_ptr)
{
    const int k    = blockIdx.x;
    const int b    = blockIdx.y;
    const int tid  = threadIdx.x;
    const int lane = tid & 63;
    const int grp  = tid >> 6;
    const int base = k * CHUNK;

    __shared__ int    scs[CHUNK];
    __shared__ int    sn;
    __shared__ float4 sm[8][64];

    if (tid < CHUNK) scs[tid] = cs[base + tid];
    if (tid == 0)    sn = *n_ptr;
    __syncthreads();

    const int n = sn;
    const float* p = hs + ((size_t)b * N_ + base) * HD + lane * 4;

    float4 s = make_float4(0.f, 0.f, 0.f, 0.f);
#pragma unroll 16
    for (int i = grp; i < CHUNK; i += 8) {
        float4 v = *(const float4*)(p + (size_t)i * HD);   // always in-bounds
        if (((base + i) < n) & (scs[i] == k)) {
            s.x += v.x; s.y += v.y; s.z += v.z; s.w += v.w;
        }
    }
    sm[grp][lane] = s;
    __syncthreads();

    if (grp == 0) {
        float4 t = sm[0][lane];
#pragma unroll
        for (int g = 1; g < 8; ++g) {
            float4 u = sm[g][lane];
            t.x += u.x; t.y += u.y; t.z += u.z; t.w += u.w;
        }
        ((float4*)(d_Hk + (size_t)(b * KC + k) * HD))[lane] = t;
    }
}

// ---------------------------------------------------------------------------
// GEMM: 64x128 tile, BK=16, 128 threads, 8x8 per thread (1.0 B LDS per FMA:
// crossbar and FFMA2 pipe co-saturate). Double-buffered, register prefetch.
// K-slice is always 256; blockIdx.z picks the slice (split-K for gemm2).
// DUAL: gemm1 — by = batch, rows = its 64 Hk rows; epilogue writes
//       relu(X+b1) and relu(X+y+b1) into d_h1. Else: C partial rows,
//       bias added only on z==0.
// ---------------------------------------------------------------------------
#define ASTR 68
#define BSTR 132

template<bool DUAL>
__global__ __launch_bounds__(128, 3)
void gemm8x8_kernel(const float* __restrict__ A, int lda,
                    const float* __restrict__ W,
                    const float* __restrict__ bias,
                    float* __restrict__ C,
                    int M, int Nn)
{
    constexpr int KS = 256;            // K per slice
    __shared__ float As[2][16][ASTR];
    __shared__ float Bs[2][16][BSTR];

    const int tid = threadIdx.x;
    const int tx  = tid & 15;          // 8 cols each -> 128
    const int ty  = tid >> 4;          // 8 rows each -> 64
    const int m0  = blockIdx.y * 64;
    const int n0  = blockIdx.x * 128;
    const int z   = blockIdx.z;

    const float* Az = A + z * KS;
    const float* Wz = W + (size_t)z * KS * Nn;
    float*       Cz = C + (size_t)z * M * Nn;

    // A loader: 2 threads/row, 8 k-floats each
    const int ar = tid >> 1;           // 0..63
    const int ac = (tid & 1) * 8;
    const bool a_ok = (m0 + ar) < M;
    const float* aptr = Az + (size_t)(m0 + ar) * lda + ac;

    // B loader: 4 float4 per thread over 16x128 tile
    int brow[4], bcol[4];
#pragma unroll
    for (int t = 0; t < 4; ++t) {
        const int idx4 = tid + t * 128;
        brow[t] = idx4 >> 5;           // 32 float4 per row
        bcol[t] = (idx4 & 31) * 4;
    }

    u64 acc[8][4];
#pragma unroll
    for (int i = 0; i < 8; ++i)
#pragma unroll
        for (int j = 0; j < 4; ++j) acc[i][j] = 0ull;

    // prologue
    float4 pa0 = make_float4(0,0,0,0), pa1 = pa0;
    float4 pb[4];
    if (a_ok) { pa0 = *(const float4*)aptr; pa1 = *(const float4*)(aptr + 4); }
#pragma unroll
    for (int t = 0; t < 4; ++t)
        pb[t] = *(const float4*)(Wz + (size_t)brow[t] * Nn + n0 + bcol[t]);

    As[0][ac+0][ar] = pa0.x; As[0][ac+1][ar] = pa0.y;
    As[0][ac+2][ar] = pa0.z; As[0][ac+3][ar] = pa0.w;
    As[0][ac+4][ar] = pa1.x; As[0][ac+5][ar] = pa1.y;
    As[0][ac+6][ar] = pa1.z; As[0][ac+7][ar] = pa1.w;
#pragma unroll
    for (int t = 0; t < 4; ++t)
        *(float4*)&Bs[0][brow[t]][bcol[t]] = pb[t];
    __syncthreads();

    int buf = 0;
    for (int k0 = 0; k0 < KS; k0 += 16) {
        const int k1 = k0 + 16;
        const bool more = (k1 < KS);

        if (more) {
            if (a_ok) {
                pa0 = *(const float4*)(aptr + k1);
                pa1 = *(const float4*)(aptr + k1 + 4);
            }
#pragma unroll
            for (int t = 0; t < 4; ++t)
                pb[t] = *(const float4*)(Wz + (size_t)(k1 + brow[t]) * Nn + n0 + bcol[t]);
        }

#pragma unroll
        for (int kk = 0; kk < 16; ++kk) {
            float4 a0 = *(const float4*)&As[buf][kk][ty * 8];
            float4 a1 = *(const float4*)&As[buf][kk][ty * 8 + 4];
            const u64* bp = (const u64*)&Bs[buf][kk][tx * 8];
            const u64 b0 = bp[0], b1v = bp[1], b2 = bp[2], b3 = bp[3];

            const float av[8] = {a0.x, a0.y, a0.z, a0.w, a1.x, a1.y, a1.z, a1.w};
#pragma unroll
            for (int i = 0; i < 8; ++i) {
                const u64 ad = dup2(av[i]);
                ffma2(acc[i][0], ad, b0); ffma2(acc[i][1], ad, b1v);
                ffma2(acc[i][2], ad, b2); ffma2(acc[i][3], ad, b3);
            }
        }

        if (more) {
            const int nb = buf ^ 1;
            As[nb][ac+0][ar] = pa0.x; As[nb][ac+1][ar] = pa0.y;
            As[nb][ac+2][ar] = pa0.z; As[nb][ac+3][ar] = pa0.w;
            As[nb][ac+4][ar] = pa1.x; As[nb][ac+5][ar] = pa1.y;
            As[nb][ac+6][ar] = pa1.z; As[nb][ac+7][ar] = pa1.w;
#pragma unroll
            for (int t = 0; t < 4; ++t)
                *(float4*)&Bs[nb][brow[t]][bcol[t]] = pb[t];
            __syncthreads();
            buf = nb;
        }
    }

    // epilogue
    const int gn0 = n0 + tx * 8;
    const float4 bv0 = *(const float4*)(bias + gn0);
    const float4 bv1 = *(const float4*)(bias + gn0 + 4);

    if (DUAL) {
        const int b = blockIdx.y;      // batch; tile rows = k 0..63
        const float4 yv0 = *(const float4*)(d_y + (size_t)b * GH + gn0);
        const float4 yv1 = *(const float4*)(d_y + (size_t)b * GH + gn0 + 4);
        float* h1b = d_h1 + (size_t)b * ROWS * GH + gn0;
#pragma unroll
        for (int i = 0; i < 8; ++i) {
            const int k = ty * 8 + i;
            float2 p0 = unpk(acc[i][0]), p1 = unpk(acc[i][1]);
            float2 p2 = unpk(acc[i][2]), p3 = unpk(acc[i][3]);
            float x0 = p0.x + bv0.x, x1 = p0.y + bv0.y;
            float x2 = p1.x + bv0.z, x3 = p1.y + bv0.w;
            float x4 = p2.x + bv1.x, x5 = p2.y + bv1.y;
            float x6 = p3.x + bv1.z, x7 = p3.y + bv1.w;
            float* r0 = h1b + (size_t)k * GH;
            *(float4*)r0       = make_float4(fmaxf(x0,0.f), fmaxf(x1,0.f), fmaxf(x2,0.f), fmaxf(x3,0.f));
            *(float4*)(r0 + 4) = make_float4(fmaxf(x4,0.f), fmaxf(x5,0.f), fmaxf(x6,0.f), fmaxf(x7,0.f));
            float* r1 = h1b + (size_t)(KC + k) * GH;
            *(float4*)r1       = make_float4(fmaxf(x0+yv0.x,0.f), fmaxf(x1+yv0.y,0.f),
                                             fmaxf(x2+yv0.z,0.f), fmaxf(x3+yv0.w,0.f));
            *(float4*)(r1 + 4) = make_float4(fmaxf(x4+yv1.x,0.f), fmaxf(x5+yv1.y,0.f),
                                             fmaxf(x6+yv1.z,0.f), fmaxf(x7+yv1.w,0.f));
        }
    } else {
        const bool addb = (z == 0);
#pragma unroll
        for (int i = 0; i < 8; ++i) {
            const int gm = m0 + ty * 8 + i;
            if (gm >= M) continue;
            float2 p0 = unpk(acc[i][0]), p1 = unpk(acc[i][1]);
            float2 p2 = unpk(acc[i][2]), p3 = unpk(acc[i][3]);
            float o0 = p0.x, o1 = p0.y, o2 = p1.x, o3 = p1.y;
            float o4 = p2.x, o5 = p2.y, o6 = p3.x, o7 = p3.y;
            if (addb) {
                o0 += bv0.x; o1 += bv0.y; o2 += bv0.z; o3 += bv0.w;
                o4 += bv1.x; o5 += bv1.y; o6 += bv1.z; o7 += bv1.w;
            }
            float* cp = Cz + (size_t)gm * Nn + gn0;
            *(float4*)cp       = make_float4(o0, o1, o2, o3);
            *(float4*)(cp + 4) = make_float4(o4, o5, o6, o7);
        }
    }
}

// ---------------------------------------------------------------------------
// Kernel 4: partial S over both split-K partials. Grid (4, B).
// ---------------------------------------------------------------------------
__global__ void s_partial_kernel()
{
    const int q = blockIdx.x;
    const int b = blockIdx.y;
    const int h = threadIdx.x;
    const float* g0 = d_gs + (size_t)b * ROWS * GD;
    const float* g1 = g0 + (size_t)M_TOT * GD;

    float s = 0.f;
#pragma unroll
    for (int j = q * 16; j < q * 16 + 16; ++j)
        s += g0[(size_t)j * GD + h] + g1[(size_t)j * GD + h];
    d_Sp[((size_t)q * B_ + b) * GD + h] = s;
}

// ---------------------------------------------------------------------------
// Kernel 5: finalize. Grid (K+1, B), 256 threads.
// ---------------------------------------------------------------------------
__global__ void finalize_kernel(float* __restrict__ out)
{
    const int k = blockIdx.x;
    const int b = blockIdx.y;
    const int h = threadIdx.x;

    float S = d_Sp[((size_t)0 * B_ + b) * GD + h]
            + d_Sp[((size_t)1 * B_ + b) * GD + h]
            + d_Sp[((size_t)2 * B_ + b) * GD + h]
            + d_Sp[((size_t)3 * B_ + b) * GD + h];

    const float* g0 = d_gs + (size_t)b * ROWS * GD;
    const float* g1 = g0 + (size_t)M_TOT * GD;

    float v;
    if (k < KC)
        v = S - (g0[(size_t)k * GD + h] + g1[(size_t)k * GD + h])
              + (g0[(size_t)(KC + k) * GD + h] + g1[(size_t)(KC + k) * GD + h]);
    else
        v = S + (g0[(size_t)(2 * KC) * GD + h] + g1[(size_t)(2 * KC) * GD + h]);
    out[((size_t)b * (KC + 1) + k) * GD + h] = v;
}

// ---------------------------------------------------------------------------
extern "C" void kernel_launch(void* const* d_in, const int* in_sizes, int n_in,
                              void* d_out, int out_size)
{
    const float* hs = (const float*)d_in[0];
    const int*   cs = (const int*)  d_in[1];
    const float* W1 = (const float*)d_in[2];
    const float* b1 = (const float*)d_in[3];
    const float* W2 = (const float*)d_in[4];
    const float* b2 = (const float*)d_in[5];
    const int*   np = (const int*)  d_in[6];
    float* out = (float*)d_out;

    float *pHk, *pH1, *pGS;
    cudaGetSymbolAddress((void**)&pHk, d_Hk);
    cudaGetSymbolAddress((void**)&pH1, d_h1);
    cudaGetSymbolAddress((void**)&pGS, d_gs);

    // idx0: prep (y = hn@W1, h1 row 2K, mask)
    prep_kernel<<<dim3(4, B_), 128>>>(hs, np, W1, b1, out);

    // idx1: clustered reduce -> compact Hk
    reduce_kernel<<<dim3(KC, B_), 512>>>(hs, cs, np);

    // idx2: gemm1 X = Hk@W1, dual relu epilogue (grid 4x32 = 128 CTAs)
    gemm8x8_kernel<true><<<dim3(GH / 128, B_, 1), 128>>>(pHk, HD, W1, b1, nullptr, B_ * KC, GH);

    // idx3: gemm2 h1@W2, split-K=2 (grid 2x65x2 = 260 CTAs)   <- profiled slot
    gemm8x8_kernel<false><<<dim3(GD / 128, (M_TOT + 63) / 64, 2), 128>>>(pH1, GH, W2, b2, pGS, M_TOT, GD);

    // idx4: S partials
    s_partial_kernel<<<dim3(4, B_), 256>>>();

    // idx5: finalize
    finalize_kernel<<<dim3(KC + 1, B_), 256>>>(out);
}

// round 16
// speedup vs baseline: 1.2002x; 1.0301x over previous
#include <cuda_runtime.h>

#define B_    32
#define N_    8192
#define HD    256     // H_DIM
#define GH    512     // G_HID
#define GD    256     // G_DIM
#define KC    64      // K
#define CHUNK 128     // N_/KC
#define ROWS  129     // 2K+1
#define M_TOT 4128    // B_*ROWS

typedef unsigned long long u64;

// Scratch (static device globals — no allocation allowed)
__device__ float d_Hk[B_ * KC * HD];       // 2 MB   compact Hk rows
__device__ float d_y [B_ * GH];            // 64 KB  hn @ W1
__device__ float d_h1[M_TOT * GH];         // 8.4 MB
__device__ float d_gs[2 * M_TOT * GD];     // 8.4 MB (split-K partials)
__device__ float d_Sp[4 * B_ * GD];

// ---------------------------------------------------------------------------
// packed f32x2 + cp.async helpers
// ---------------------------------------------------------------------------
__device__ __forceinline__ u64 dup2(float x) {
    unsigned xi = __float_as_uint(x);
    u64 r;
    asm("mov.b64 %0, {%1, %1};" : "=l"(r) : "r"(xi));
    return r;
}
__device__ __forceinline__ void ffma2(u64& d, u64 a, u64 b) {
    asm("fma.rn.f32x2 %0, %1, %2, %0;" : "+l"(d) : "l"(a), "l"(b));
}
__device__ __forceinline__ float2 unpk(u64 v) {
    unsigned lo, hi;
    asm("mov.b64 {%0, %1}, %2;" : "=r"(lo), "=r"(hi) : "l"(v));
    return make_float2(__uint_as_float(lo), __uint_as_float(hi));
}
__device__ __forceinline__ void cp16(void* smem_dst, const void* gmem_src) {
    unsigned d = (unsigned)__cvta_generic_to_shared(smem_dst);
    asm volatile("cp.async.cg.shared.global [%0], [%1], 16;" :: "r"(d), "l"(gmem_src));
}
__device__ __forceinline__ void cp_commit() {
    asm volatile("cp.async.commit_group;");
}
__device__ __forceinline__ void cp_wait0() {
    asm volatile("cp.async.wait_group 0;");
}

// ---------------------------------------------------------------------------
// Kernel 0 (idx0): prep — y[b] = hn[b] @ W1; h1 row 2K = relu(y+b1); mask.
// ---------------------------------------------------------------------------
__global__ __launch_bounds__(128)
void prep_kernel(const float* __restrict__ hs,
                 const int*   __restrict__ np,
                 const float* __restrict__ W1,
                 const float* __restrict__ b1,
                 float* __restrict__ out)
{
    const int nc  = blockIdx.x;
    const int b   = blockIdx.y;
    const int tid = threadIdx.x;
    const int n   = nc * 128 + tid;

    __shared__ float hn_s[HD];
    const int nrow = *np;
    for (int i = tid; i < HD; i += 128)
        hn_s[i] = hs[((size_t)b * N_ + nrow) * HD + i];
    __syncthreads();

    float a0 = 0.f, a1 = 0.f, a2 = 0.f, a3 = 0.f;
#pragma unroll 4
    for (int h = 0; h < HD; h += 4) {
        a0 += hn_s[h]     * W1[(size_t)h       * GH + n];
        a1 += hn_s[h + 1] * W1[(size_t)(h + 1) * GH + n];
        a2 += hn_s[h + 2] * W1[(size_t)(h + 2) * GH + n];
        a3 += hn_s[h + 3] * W1[(size_t)(h + 3) * GH + n];
    }
    const float y = (a0 + a1) + (a2 + a3);
    d_y[(size_t)b * GH + n] = y;
    d_h1[((size_t)b * ROWS + 2 * KC) * GH + n] = fmaxf(y + b1[n], 0.f);

    if (nc == 0 && b == 0) {
        float* mask = out + (size_t)B_ * (KC + 1) * GD;
        for (int i = tid; i < B_ * (KC + 1); i += 128)
            mask[i] = 1.0f;
    }
}

// ---------------------------------------------------------------------------
// Kernel 1 (idx1): clustered reduction -> compact d_Hk. Grid (K,B), 512 thr.
// ---------------------------------------------------------------------------
__global__ __launch_bounds__(512)
void reduce_kernel(const float* __restrict__ hs,
                   const int*   __restrict__ cs,
                   const int*   __restrict__ n_ptr)
{
    const int k    = blockIdx.x;
    const int b    = blockIdx.y;
    const int tid  = threadIdx.x;
    const int lane = tid & 63;
    const int grp  = tid >> 6;
    const int base = k * CHUNK;

    __shared__ int    scs[CHUNK];
    __shared__ int    sn;
    __shared__ float4 sm[8][64];

    if (tid < CHUNK) scs[tid] = cs[base + tid];
    if (tid == 0)    sn = *n_ptr;
    __syncthreads();

    const int n = sn;
    const float* p = hs + ((size_t)b * N_ + base) * HD + lane * 4;

    float4 s = make_float4(0.f, 0.f, 0.f, 0.f);
#pragma unroll 16
    for (int i = grp; i < CHUNK; i += 8) {
        float4 v = *(const float4*)(p + (size_t)i * HD);   // always in-bounds
        if (((base + i) < n) & (scs[i] == k)) {
            s.x += v.x; s.y += v.y; s.z += v.z; s.w += v.w;
        }
    }
    sm[grp][lane] = s;
    __syncthreads();

    if (grp == 0) {
        float4 t = sm[0][lane];
#pragma unroll
        for (int g = 1; g < 8; ++g) {
            float4 u = sm[g][lane];
            t.x += u.x; t.y += u.y; t.z += u.z; t.w += u.w;
        }
        ((float4*)(d_Hk + (size_t)(b * KC + k) * HD))[lane] = t;
    }
}

// ---------------------------------------------------------------------------
// GEMM: BM x 128 tile (BM = 8*TM), BK=16, 128 threads, TM x 8 per thread.
// B tile streamed via cp.async (no reg prefetch); A via reg round-trip
// (needs transpose). Double-buffered. K-slice fixed at 256; blockIdx.z
// selects the slice (split-K for gemm2; bias only on z==0).
// DUAL (TM=4): gemm1 — by -> (batch, half); epilogue writes relu(X+b1) and
// relu(X+y+b1) rows of d_h1.
// ---------------------------------------------------------------------------
template<int TM, bool DUAL>
__global__ __launch_bounds__(128, (TM == 8) ? 3 : 4)
void gemm_cp_kernel(const float* __restrict__ A, int lda,
                    const float* __restrict__ W,
                    const float* __restrict__ bias,
                    float* __restrict__ C,
                    int M, int Nn)
{
    constexpr int KS   = 256;
    constexpr int BM   = 8 * TM;
    constexpr int NA   = BM / 32;        // float4 A-loads per thread (1 or 2)
    constexpr int ASTR = BM + 4;

    __shared__ float As[2][16][ASTR];
    __shared__ float Bs[2][16][132];

    const int tid = threadIdx.x;
    const int tx  = tid & 15;
    const int ty  = tid >> 4;
    const int m0  = blockIdx.y * BM;
    const int n0  = blockIdx.x * 128;
    const int z   = blockIdx.z;

    const float* Az = A + z * KS;
    const float* Wz = W + (size_t)z * KS * Nn;
    float*       Cz = C + (size_t)z * M * Nn;

    // A loader: NA float4 per thread
    int arow[NA], acol[NA];
    bool aok[NA];
    const float* aptr[NA];
#pragma unroll
    for (int t = 0; t < NA; ++t) {
        const int idx = tid + t * 128;
        arow[t] = idx >> 2;
        acol[t] = (idx & 3) * 4;
        aok[t]  = (m0 + arow[t]) < M;
        aptr[t] = Az + (size_t)(m0 + arow[t]) * lda + acol[t];
    }

    // B loader: 4 cp.async(16B) per thread over 16x128 tile
    int brow[4], bcol[4];
#pragma unroll
    for (int t = 0; t < 4; ++t) {
        const int idx4 = tid + t * 128;
        brow[t] = idx4 >> 5;
        bcol[t] = (idx4 & 31) * 4;
    }

    u64 acc[TM][4];
#pragma unroll
    for (int i = 0; i < TM; ++i)
#pragma unroll
        for (int j = 0; j < 4; ++j) acc[i][j] = 0ull;

    // prologue: stage 0
    float4 pa[NA];
#pragma unroll
    for (int t = 0; t < NA; ++t)
        pa[t] = aok[t] ? *(const float4*)aptr[t] : make_float4(0,0,0,0);
#pragma unroll
    for (int t = 0; t < 4; ++t)
        cp16(&Bs[0][brow[t]][bcol[t]], Wz + (size_t)brow[t] * Nn + n0 + bcol[t]);
    cp_commit();
#pragma unroll
    for (int t = 0; t < NA; ++t) {
        As[0][acol[t]+0][arow[t]] = pa[t].x;
        As[0][acol[t]+1][arow[t]] = pa[t].y;
        As[0][acol[t]+2][arow[t]] = pa[t].z;
        As[0][acol[t]+3][arow[t]] = pa[t].w;
    }
    cp_wait0();
    __syncthreads();

    int buf = 0;
    for (int k0 = 0; k0 < KS; k0 += 16) {
        const int k1 = k0 + 16;
        const bool more = (k1 < KS);
        const int nb = buf ^ 1;

        if (more) {
#pragma unroll
            for (int t = 0; t < NA; ++t)
                if (aok[t]) pa[t] = *(const float4*)(aptr[t] + k1);
#pragma unroll
            for (int t = 0; t < 4; ++t)
                cp16(&Bs[nb][brow[t]][bcol[t]],
                     Wz + (size_t)(k1 + brow[t]) * Nn + n0 + bcol[t]);
            cp_commit();
        }

#pragma unroll
        for (int kk = 0; kk < 16; ++kk) {
            float4 aq[TM / 4];
#pragma unroll
            for (int c = 0; c < TM / 4; ++c)
                aq[c] = *(const float4*)&As[buf][kk][ty * TM + 4 * c];
            const u64* bp = (const u64*)&Bs[buf][kk][tx * 8];
            const u64 b0 = bp[0], b1v = bp[1], b2 = bp[2], b3 = bp[3];

#pragma unroll
            for (int c = 0; c < TM / 4; ++c) {
                const float av[4] = {aq[c].x, aq[c].y, aq[c].z, aq[c].w};
#pragma unroll
                for (int i = 0; i < 4; ++i) {
                    const int r = c * 4 + i;
                    const u64 ad = dup2(av[i]);
                    ffma2(acc[r][0], ad, b0); ffma2(acc[r][1], ad, b1v);
                    ffma2(acc[r][2], ad, b2); ffma2(acc[r][3], ad, b3);
                }
            }
        }

        if (more) {
            cp_wait0();
#pragma unroll
            for (int t = 0; t < NA; ++t) {
                As[nb][acol[t]+0][arow[t]] = pa[t].x;
                As[nb][acol[t]+1][arow[t]] = pa[t].y;
                As[nb][acol[t]+2][arow[t]] = pa[t].z;
                As[nb][acol[t]+3][arow[t]] = pa[t].w;
            }
            __syncthreads();
            buf = nb;
        }
    }

    // epilogue
    const int gn0 = n0 + tx * 8;
    const float4 bv0 = *(const float4*)(bias + gn0);
    const float4 bv1 = *(const float4*)(bias + gn0 + 4);

    if (DUAL) {
        // TM==4: by -> (batch, half); local rows 0..31 => k = half*32 + local
        const int b    = blockIdx.y >> 1;
        const int half = blockIdx.y & 1;
        const float4 yv0 = *(const float4*)(d_y + (size_t)b * GH + gn0);
        const float4 yv1 = *(const float4*)(d_y + (size_t)b * GH + gn0 + 4);
        float* h1b = d_h1 + (size_t)b * ROWS * GH + gn0;
#pragma unroll
        for (int i = 0; i < TM; ++i) {
            const int k = half * 32 + ty * TM + i;
            float2 p0 = unpk(acc[i][0]), p1 = unpk(acc[i][1]);
            float2 p2 = unpk(acc[i][2]), p3 = unpk(acc[i][3]);
            float x0 = p0.x + bv0.x, x1 = p0.y + bv0.y;
            float x2 = p1.x + bv0.z, x3 = p1.y + bv0.w;
            float x4 = p2.x + bv1.x, x5 = p2.y + bv1.y;
            float x6 = p3.x + bv1.z, x7 = p3.y + bv1.w;
            float* r0 = h1b + (size_t)k * GH;
            *(float4*)r0       = make_float4(fmaxf(x0,0.f), fmaxf(x1,0.f), fmaxf(x2,0.f), fmaxf(x3,0.f));
            *(float4*)(r0 + 4) = make_float4(fmaxf(x4,0.f), fmaxf(x5,0.f), fmaxf(x6,0.f), fmaxf(x7,0.f));
            float* r1 = h1b + (size_t)(KC + k) * GH;
            *(float4*)r1       = make_float4(fmaxf(x0+yv0.x,0.f), fmaxf(x1+yv0.y,0.f),
                                             fmaxf(x2+yv0.z,0.f), fmaxf(x3+yv0.w,0.f));
            *(float4*)(r1 + 4) = make_float4(fmaxf(x4+yv1.x,0.f), fmaxf(x5+yv1.y,0.f),
                                             fmaxf(x6+yv1.z,0.f), fmaxf(x7+yv1.w,0.f));
        }
    } else {
        const bool addb = (z == 0);
#pragma unroll
        for (int i = 0; i < TM; ++i) {
            const int gm = m0 + ty * TM + i;
            if (gm >= M) continue;
            float2 p0 = unpk(acc[i][0]), p1 = unpk(acc[i][1]);
            float2 p2 = unpk(acc[i][2]), p3 = unpk(acc[i][3]);
            float o0 = p0.x, o1 = p0.y, o2 = p1.x, o3 = p1.y;
            float o4 = p2.x, o5 = p2.y, o6 = p3.x, o7 = p3.y;
            if (addb) {
                o0 += bv0.x; o1 += bv0.y; o2 += bv0.z; o3 += bv0.w;
                o4 += bv1.x; o5 += bv1.y; o6 += bv1.z; o7 += bv1.w;
            }
            float* cp = Cz + (size_t)gm * Nn + gn0;
            *(float4*)cp       = make_float4(o0, o1, o2, o3);
            *(float4*)(cp + 4) = make_float4(o4, o5, o6, o7);
        }
    }
}

// ---------------------------------------------------------------------------
// Kernel 4: partial S over both split-K partials. Grid (4, B).
// ---------------------------------------------------------------------------
__global__ void s_partial_kernel()
{
    const int q = blockIdx.x;
    const int b = blockIdx.y;
    const int h = threadIdx.x;
    const float* g0 = d_gs + (size_t)b * ROWS * GD;
    const float* g1 = g0 + (size_t)M_TOT * GD;

    float s = 0.f;
#pragma unroll
    for (int j = q * 16; j < q * 16 + 16; ++j)
        s += g0[(size_t)j * GD + h] + g1[(size_t)j * GD + h];
    d_Sp[((size_t)q * B_ + b) * GD + h] = s;
}

// ---------------------------------------------------------------------------
// Kernel 5: finalize. Grid (K+1, B), 256 threads.
// ---------------------------------------------------------------------------
__global__ void finalize_kernel(float* __restrict__ out)
{
    const int k = blockIdx.x;
    const int b = blockIdx.y;
    const int h = threadIdx.x;

    float S = d_Sp[((size_t)0 * B_ + b) * GD + h]
            + d_Sp[((size_t)1 * B_ + b) * GD + h]
            + d_Sp[((size_t)2 * B_ + b) * GD + h]
            + d_Sp[((size_t)3 * B_ + b) * GD + h];

    const float* g0 = d_gs + (size_t)b * ROWS * GD;
    const float* g1 = g0 + (size_t)M_TOT * GD;

    float v;
    if (k < KC)
        v = S - (g0[(size_t)k * GD + h] + g1[(size_t)k * GD + h])
              + (g0[(size_t)(KC + k) * GD + h] + g1[(size_t)(KC + k) * GD + h]);
    else
        v = S + (g0[(size_t)(2 * KC) * GD + h] + g1[(size_t)(2 * KC) * GD + h]);
    out[((size_t)b * (KC + 1) + k) * GD + h] = v;
}

// ---------------------------------------------------------------------------
extern "C" void kernel_launch(void* const* d_in, const int* in_sizes, int n_in,
                              void* d_out, int out_size)
{
    const float* hs = (const float*)d_in[0];
    const int*   cs = (const int*)  d_in[1];
    const float* W1 = (const float*)d_in[2];
    const float* b1 = (const float*)d_in[3];
    const float* W2 = (const float*)d_in[4];
    const float* b2 = (const float*)d_in[5];
    const int*   np = (const int*)  d_in[6];
    float* out = (float*)d_out;

    float *pHk, *pH1, *pGS;
    cudaGetSymbolAddress((void**)&pHk, d_Hk);
    cudaGetSymbolAddress((void**)&pH1, d_h1);
    cudaGetSymbolAddress((void**)&pGS, d_gs);

    // idx0: prep (y = hn@W1, h1 row 2K, mask)
    prep_kernel<<<dim3(4, B_), 128>>>(hs, np, W1, b1, out);

    // idx1: clustered reduce -> compact Hk
    reduce_kernel<<<dim3(KC, B_), 512>>>(hs, cs, np);

    // idx2: gemm1 X = Hk@W1, dual relu epilogue (32x128 tiles, 256 CTAs)
    gemm_cp_kernel<4, true><<<dim3(GH / 128, 2 * B_, 1), 128>>>(pHk, HD, W1, b1, nullptr, B_ * KC, GH);

    // idx3: gemm2 h1@W2, split-K=2 (64x128 tiles, 260 CTAs)   <- profiled slot
    gemm_cp_kernel<8, false><<<dim3(GD / 128, (M_TOT + 63) / 64, 2), 128>>>(pH1, GH, W2, b2, pGS, M_TOT, GD);

    // idx4: S partials
    s_partial_kernel<<<dim3(4, B_), 256>>>();

    // idx5: finalize
    finalize_kernel<<<dim3(KC + 1, B_), 256>>>(out);
}